// round 17
// baseline (speedup 1.0000x reference)
#include <cuda_runtime.h>
#include <math_constants.h>
#include <cstdint>

// Problem constants
#define HH   8
#define BB   16
#define GG   513
#define DD   256
#define DKC  32
#define EE   256
#define NPP  256
#define MROWS (BB*GG)            // 8208
#define MHALF (BB*NPP)           // 4096
#define PER  (HH*BB*GG*DKC)      // 2101248
#define NORMC 0.17677669529663687f
#define SCL  (NORMC * 1.4426950408889634f)   // NORMC * log2(e)

// attn smem layout (float offsets)
#define PADM 516
#define LPAD 520
#define OFF_KT  0
#define OFF_VT  16512
#define OFF_L0  33024
#define OFF_LX  41344
#define OFF_QB  49664
#define OFF_U1  50176
#define OFF_U2  50688
#define OFF_QA  51200
#define OFF_TOT 51712
#define SMEM_FLOATS 51728        // 206912 bytes

typedef unsigned long long u64;
typedef unsigned int u32;

// packed f32x2 helpers (Blackwell FFMA2 path)
__device__ __forceinline__ u64 pk2(float lo, float hi) {
    u64 r; asm("mov.b64 %0, {%1, %2};" : "=l"(r) : "f"(lo), "f"(hi)); return r;
}
__device__ __forceinline__ float2 upk2(u64 v) {
    float2 f; asm("mov.b64 {%0, %1}, %2;" : "=f"(f.x), "=f"(f.y) : "l"(v)); return f;
}
#define FMA2(d, a, b) asm("fma.rn.f32x2 %0, %1, %2, %0;" : "+l"(d) : "l"(a), "l"(b))

__device__ __forceinline__ float ex2(float x) {
    float r; asm("ex2.approx.ftz.f32 %0, %1;" : "=f"(r) : "f"(x)); return r;
}

// cp.async helpers
__device__ __forceinline__ void cpa16(u32 dst, const float* src, int sz) {
    asm volatile("cp.async.ca.shared.global [%0], [%1], 16, %2;"
                 :: "r"(dst), "l"(src), "r"(sz));
}
#define CP_COMMIT() asm volatile("cp.async.commit_group;" ::: "memory")
#define CP_WAIT1()  asm volatile("cp.async.wait_group 1;" ::: "memory")
#define CP_WAIT0()  asm volatile("cp.async.wait_group 0;" ::: "memory")

// Scratch (device globals; no allocation allowed)
__device__ float g_Q [PER];
__device__ float g_K [PER];
__device__ float g_V [PER];
__device__ float g_Q1[PER];
__device__ float g_Q2[PER];
__device__ float g_Q3[PER];
__device__ float g_Q4[PER];
__device__ float g_Q5[PER];
__device__ float g_Q6[PER];
__device__ float g_Hd[PER];

// ---------------------------------------------------------------------------
// Kernel A: projection GEMMs. 128x128 tile, 8x8 micro-tile (f32x2 packed),
// cp.async DOUBLE-BUFFERED K-pipeline (16-wide chunks), flat 774-CTA grid:
//   [0,390): full targets 0..2 (130 CTAs each); [390,774): half targets 3..8.
// A stored row-major [row][16] (pad 20) in smem; read via broadcast scalar LDS.
// ---------------------------------------------------------------------------
__global__ __launch_bounds__(256, 2) void proj_gemm(
    const float* __restrict__ qsrc, const float* __restrict__ hsrc,
    const float* __restrict__ Wq,  const float* __restrict__ Wk,
    const float* __restrict__ Wv,  const float* __restrict__ W1,
    const float* __restrict__ W2,  const float* __restrict__ W3,
    const float* __restrict__ W4,  const float* __restrict__ W5,
    const float* __restrict__ W6)
{
    const int bx = blockIdx.x;
    int t, mtile, ntile;
    if (bx < 390) {
        t = bx / 130;
        int r = bx % 130;
        ntile = r / 65;
        mtile = r % 65;
    } else {
        int r = bx - 390;
        t = 3 + (r >> 6);
        int rr = r & 63;
        ntile = rr >> 5;
        mtile = rr & 31;
    }
    const bool half = (t >= 3);
    const int nodeoff = (t >= 6) ? (1 + NPP) : 1;
    const int Mtot = half ? MHALF : MROWS;

    const float* src = (t == 0) ? qsrc : hsrc;
    const float* W;
    float* outp;
    switch (t) {
        case 0: W = Wq; outp = g_Q;  break;
        case 1: W = Wk; outp = g_K;  break;
        case 2: W = Wv; outp = g_V;  break;
        case 3: W = W1; outp = g_Q1; break;
        case 4: W = W2; outp = g_Q2; break;
        case 5: W = W3; outp = g_Q3; break;
        case 6: W = W4; outp = g_Q4; break;
        case 7: W = W5; outp = g_Q5; break;
        default: W = W6; outp = g_Q6; break;
    }

    __shared__ float Ash[2][128][20];    // [buf][row][d] row-major, pad 20
    __shared__ float Bsh[2][16][132];    // [buf][d][n]

    const int tid = threadIdx.x;
    const int m0 = mtile * 128;
    const int n0 = ntile * 128;
    const int cx = tid & 15;
    const int ry = tid >> 4;

    // Precompute per-thread copy descriptors.
    // A: 2 chunks of 16B: fid = tid + i*256; row = fid>>2 (0..127), dch = fid&3.
    const float* asrc[2];
    u32 adst[2][2];
    int asz[2];
#pragma unroll
    for (int i = 0; i < 2; i++) {
        int fid = tid + i * 256;
        int row = fid >> 2, dch = fid & 3;
        int m = m0 + row;
        bool valid = (m < Mtot);
        size_t srow = 0;
        if (valid)
            srow = half ? ((size_t)(m >> 8) * GG + nodeoff + (m & 255))
                        : (size_t)m;
        asrc[i] = src + srow * 256 + dch * 4;   // + d0 later
        asz[i]  = valid ? 16 : 0;
        adst[0][i] = (u32)__cvta_generic_to_shared(&Ash[0][row][dch * 4]);
        adst[1][i] = (u32)__cvta_generic_to_shared(&Ash[1][row][dch * 4]);
    }
    // B: 2 chunks of 16B: fid = tid + i*256; d = fid>>5 (0..15), nn = (fid&31)*4.
    const float* bsrc[2];
    u32 bdst[2][2];
#pragma unroll
    for (int i = 0; i < 2; i++) {
        int fid = tid + i * 256;
        int d = fid >> 5, nn = (fid & 31) * 4;
        int n = n0 + nn;
        bsrc[i] = W + (size_t)(n >> 5) * 8192 + (size_t)d * 32 + (n & 31); // + d0*32 later
        bdst[0][i] = (u32)__cvta_generic_to_shared(&Bsh[0][d][nn]);
        bdst[1][i] = (u32)__cvta_generic_to_shared(&Bsh[1][d][nn]);
    }

    u64 acc2[8][4];
#pragma unroll
    for (int i = 0; i < 8; i++)
#pragma unroll
        for (int j = 0; j < 4; j++) acc2[i][j] = 0ull;

    // preload iteration 0 into buffer 0
#pragma unroll
    for (int i = 0; i < 2; i++) cpa16(adst[0][i], asrc[i], asz[i]);
#pragma unroll
    for (int i = 0; i < 2; i++) cpa16(bdst[0][i], bsrc[i], 16);
    CP_COMMIT();

    for (int it = 0; it < 16; it++) {
        const int cur = it & 1;
        if (it < 15) {
            const int nb = cur ^ 1;
            const int d0 = (it + 1) * 16;
#pragma unroll
            for (int i = 0; i < 2; i++) cpa16(adst[nb][i], asrc[i] + d0, asz[i]);
#pragma unroll
            for (int i = 0; i < 2; i++) cpa16(bdst[nb][i], bsrc[i] + (size_t)d0 * 32, 16);
            CP_COMMIT();
            CP_WAIT1();
        } else {
            CP_WAIT0();
        }
        __syncthreads();

#pragma unroll
        for (int d = 0; d < 16; d++) {
            float ar[8];
#pragma unroll
            for (int i = 0; i < 4; i++) {
                ar[i]     = Ash[cur][ry * 4 + i][d];
                ar[4 + i] = Ash[cur][64 + ry * 4 + i][d];
            }
            ulonglong2 b0 = *(const ulonglong2*)&Bsh[cur][d][cx * 4];
            ulonglong2 b1 = *(const ulonglong2*)&Bsh[cur][d][64 + cx * 4];
            u64 bp[4] = {b0.x, b0.y, b1.x, b1.y};
#pragma unroll
            for (int i = 0; i < 8; i++) {
                u64 a2 = pk2(ar[i], ar[i]);
#pragma unroll
                for (int j = 0; j < 4; j++)
                    FMA2(acc2[i][j], a2, bp[j]);
            }
        }
        __syncthreads();
    }

#pragma unroll
    for (int i = 0; i < 8; i++) {
        int row = (i < 4) ? (ry * 4 + i) : (64 + ry * 4 + (i - 4));
        int m = m0 + row;
        if (m >= Mtot) continue;
        int bb, node;
        if (half) { bb = m >> 8; node = nodeoff + (m & 255); }
        else      { bb = m / GG; node = m % GG; }
        float accr[8];
#pragma unroll
        for (int j = 0; j < 4; j++) {
            float2 f = upk2(acc2[i][j]);
            accr[2 * j] = f.x; accr[2 * j + 1] = f.y;
        }
#pragma unroll
        for (int j = 0; j < 8; j++) {
            int n = n0 + ((j < 4) ? (cx * 4 + j) : (64 + cx * 4 + (j - 4)));
            int hh = n >> 5, kk = n & 31;
            outp[(((size_t)hh * BB + bb) * GG + node) * DKC + kk] = accr[j];
        }
    }
}

// ---------------------------------------------------------------------------
// Kernel B: fused attention (unchanged from R15 passing version)
// ---------------------------------------------------------------------------
__device__ __forceinline__ float warpSumf(float v) {
#pragma unroll
    for (int o = 16; o; o >>= 1) v += __shfl_xor_sync(0xffffffffu, v, o);
    return v;
}

__global__ __launch_bounds__(512, 1) void attn_kernel()
{
    extern __shared__ float sm[];
    float* Kt  = sm + OFF_KT;
    float* Vt  = sm + OFF_VT;
    float* L0b = sm + OFF_L0;
    float* Lxb = sm + OFF_LX;

    const int b  = blockIdx.x;
    const int hh = blockIdx.y;
    const int tid = threadIdx.x, lane = tid & 31, wid = tid >> 5;
    const size_t base = (((size_t)hh * BB + b) * GG) * DKC;
    const float NINF = -CUDART_INF_F;

    // prefetch chunk 0's staged q-vectors (overlaps K/V smem fill)
    float nxt[4];
#pragma unroll
    for (int s = 0; s < 4; s++) {
        int i = tid + s * 512;
        int type = i >> 9, qq = (i >> 5) & 15, k = i & 31;
        int n = qq;
        float v = 0.f;
        if (n < GG) {
            size_t off = base + (size_t)n * 32 + k;
            bool pick = (n >= 1 && n <= NPP);
            if (type == 0)          v = g_Q[off];
            else if (n >= 1) {
                if (type == 1)      v = pick ? g_Q2[off] : g_Q6[off];
                else if (type == 2) v = pick ? g_Q3[off] : g_Q5[off];
                else                v = pick ? g_Q1[off] : g_Q4[off];
            }
        }
        nxt[s] = v;
    }

    if (tid < 96) {
        int k = tid / 3, cc = 513 + (tid - k * 3);
        Kt[k * PADM + cc] = 0.f;
        Vt[k * PADM + cc] = 0.f;
    }
    for (int i = tid; i < GG * DKC; i += 512) {
        int m = i >> 5, k = i & 31;
        Kt[k * PADM + m] = g_K[base + i];
        Vt[k * PADM + m] = g_V[base + i];
    }
#pragma unroll
    for (int s = 0; s < 4; s++)
        sm[OFF_QB + tid + s * 512] = nxt[s];
    __syncthreads();

    for (int c = 0; c < 33; c++) {
        const int q0 = c * 16;

        if (c + 1 < 33) {
            const int q1 = (c + 1) * 16;
#pragma unroll
            for (int s = 0; s < 4; s++) {
                int i = tid + s * 512;
                int type = i >> 9, qq = (i >> 5) & 15, k = i & 31;
                int n = q1 + qq;
                float v = 0.f;
                if (n < GG) {
                    size_t off = base + (size_t)n * 32 + k;
                    bool pick = (n >= 1 && n <= NPP);
                    if (type == 0)          v = g_Q[off];
                    else if (n >= 1) {
                        if (type == 1)      v = pick ? g_Q2[off] : g_Q6[off];
                        else if (type == 2) v = pick ? g_Q3[off] : g_Q5[off];
                        else                v = pick ? g_Q1[off] : g_Q4[off];
                    }
                }
                nxt[s] = v;
            }
        }

        // ---- Phase 2: logit GEMM (2q x 8keys, packed f32x2), SCL pre-scale ----
        {
            const int qg  = tid >> 6;
            const int qi0 = qg * 2;
            const int mt  = tid & 63;
            const int mA  = mt * 4;
            const int mB  = 256 + mt * 4;
            u64 L0p[2][4], Lxp[2][4];
#pragma unroll
            for (int q = 0; q < 2; q++)
#pragma unroll
                for (int j = 0; j < 4; j++) { L0p[q][j] = 0ull; Lxp[q][j] = 0ull; }

#pragma unroll
            for (int k4 = 0; k4 < 8; k4++) {
                float qv[2][4], u1[2][4], u2[2][4];
#pragma unroll
                for (int q = 0; q < 2; q++) {
                    *(float4*)qv[q] = *(const float4*)&sm[OFF_QB + (qi0 + q) * 32 + k4 * 4];
                    *(float4*)u1[q] = *(const float4*)&sm[OFF_U1 + (qi0 + q) * 32 + k4 * 4];
                    *(float4*)u2[q] = *(const float4*)&sm[OFF_U2 + (qi0 + q) * 32 + k4 * 4];
                }
#pragma unroll
                for (int kk = 0; kk < 4; kk++) {
                    int k = k4 * 4 + kk;
                    ulonglong2 ka = *(const ulonglong2*)&Kt[k * PADM + mA];
                    ulonglong2 kb = *(const ulonglong2*)&Kt[k * PADM + mB];
#pragma unroll
                    for (int q = 0; q < 2; q++) {
                        u64 qs2  = pk2(qv[q][kk], qv[q][kk]);
                        u64 u1s2 = pk2(u1[q][kk], u1[q][kk]);
                        u64 u2s2 = pk2(u2[q][kk], u2[q][kk]);
                        FMA2(L0p[q][0], qs2,  ka.x);
                        FMA2(L0p[q][1], qs2,  ka.y);
                        FMA2(L0p[q][2], qs2,  kb.x);
                        FMA2(L0p[q][3], qs2,  kb.y);
                        FMA2(Lxp[q][0], u1s2, ka.x);
                        FMA2(Lxp[q][1], u1s2, ka.y);
                        FMA2(Lxp[q][2], u2s2, kb.x);
                        FMA2(Lxp[q][3], u2s2, kb.y);
                    }
                }
            }
#pragma unroll
            for (int q = 0; q < 2; q++) {
                int qrow = qi0 + q;
                float2 p0 = upk2(L0p[q][0]), p1 = upk2(L0p[q][1]);
                float2 p2 = upk2(L0p[q][2]), p3 = upk2(L0p[q][3]);
                float4 oa = make_float4(p0.x*SCL, p0.y*SCL, p1.x*SCL, p1.y*SCL);
                float4 ob = make_float4(p2.x*SCL, p2.y*SCL, p3.x*SCL, p3.y*SCL);
                *(float4*)&L0b[qrow * LPAD + mA] = oa;
                *(float4*)&L0b[qrow * LPAD + mB] = ob;
                float2 x0 = upk2(Lxp[q][0]), x1 = upk2(Lxp[q][1]);
                float2 x2 = upk2(Lxp[q][2]), x3 = upk2(Lxp[q][3]);
                float4 xa = make_float4(x0.x*SCL, x0.y*SCL, x1.x*SCL, x1.y*SCL);
                float4 xb = make_float4(x2.x*SCL, x2.y*SCL, x3.x*SCL, x3.y*SCL);
                if (mt == 0) xa.x = NINF;
                *(float4*)&Lxb[qrow * LPAD + mA] = xa;
                *(float4*)&Lxb[qrow * LPAD + mB] = xb;
            }
        }
        __syncthreads();

        // ---- Phase 3: softmax, NO max-subtraction ----
        {
            int qq = wid;
            int n = q0 + qq;
            float* wrow = &L0b[qq * LPAD];
            float* xrow = &Lxb[qq * LPAD];
            if (n < GG) {
                const bool useX = (n >= 1);
                float kv512 = Kt[lane * PADM + 512];
                float4 sp;
                sp.x = sm[OFF_QB + qq*32 + lane] * kv512;
                sp.y = 0.f; sp.z = 0.f; sp.w = 0.f;
                int p = 0;
                if (useX) {
                    sp.y = sm[OFF_U2 + qq*32 + lane] * kv512;
                    p = (n <= NPP) ? n + NPP : n - NPP;
                    sp.z = sm[OFF_QA + qq*32 + lane] * Kt[lane * PADM + p];
                    sp.w = sm[OFF_U1 + qq*32 + lane] * Kt[lane * PADM + 256];
                }
#pragma unroll
                for (int o = 16; o; o >>= 1) {
                    sp.x += __shfl_xor_sync(0xffffffffu, sp.x, o);
                    sp.y += __shfl_xor_sync(0xffffffffu, sp.y, o);
                    sp.z += __shfl_xor_sync(0xffffffffu, sp.z, o);
                    sp.w += __shfl_xor_sync(0xffffffffu, sp.w, o);
                }
                if (useX) {
                    if (lane == 0) xrow[256] = SCL * sp.w;
                    __syncwarp();
                }
                float tot = 0.f;
#pragma unroll
                for (int i = 0; i < 4; i++) {
                    int m4 = i * 128 + lane * 4;
                    float4 a = *(const float4*)&wrow[m4];
                    float4 wv;
                    wv.x = ex2(a.x); wv.y = ex2(a.y);
                    wv.z = ex2(a.z); wv.w = ex2(a.w);
                    if (useX) {
                        float4 x = *(const float4*)&xrow[m4];
                        wv.x += ex2(x.x); wv.y += ex2(x.y);
                        wv.z += ex2(x.z); wv.w += ex2(x.w);
                    }
                    tot += wv.x + wv.y + wv.z + wv.w;
                    *(float4*)&wrow[m4] = wv;
                }
                tot = warpSumf(tot);
                float w512 = ex2(SCL * sp.x) + (useX ? ex2(SCL * sp.y) : 0.f);
                float wp   = useX ? ex2(SCL * sp.z) : 0.f;
                tot += w512 + wp;
                __syncwarp();
                if (lane == 0) {
                    wrow[512] = w512;
                    if (useX) wrow[p] += wp;
                    wrow[513] = 0.f; wrow[514] = 0.f; wrow[515] = 0.f;
                    sm[OFF_TOT + qq] = 1.0f / tot;
                }
            } else {
                for (int i = lane; i < 129; i += 32)
                    *(float4*)&wrow[i * 4] = make_float4(0.f, 0.f, 0.f, 0.f);
                if (lane == 0) sm[OFF_TOT + qq] = 0.f;
            }
        }
        __syncthreads();

        // ---- Phase 4: AV GEMM (warp per 32-key slice, packed f32x2) ----
        {
            u64 acc2[16];
#pragma unroll
            for (int qq = 0; qq < 16; qq++) acc2[qq] = 0ull;
            const int iters = (wid == 15) ? 9 : 8;
            const int mbase = wid * 32;
            for (int it = 0; it < iters; it++) {
                int m4 = mbase + it * 4;
                ulonglong2 v2 = *(const ulonglong2*)&Vt[lane * PADM + m4];
#pragma unroll
                for (int qq = 0; qq < 16; qq++) {
                    ulonglong2 w2 = *(const ulonglong2*)&L0b[qq * LPAD + m4];
                    FMA2(acc2[qq], w2.x, v2.x);
                    FMA2(acc2[qq], w2.y, v2.y);
                }
            }
#pragma unroll
            for (int qq = 0; qq < 16; qq++) {
                float2 f = upk2(acc2[qq]);
                Lxb[(wid * 16 + qq) * 32 + lane] = f.x + f.y;
            }
        }
        __syncthreads();

        // ---- Phase 5: 16-way reduce + writeout + commit next chunk staging ----
        {
            int qq = tid >> 5, k = tid & 31;
            float s = 0.f;
#pragma unroll
            for (int w = 0; w < 16; w++)
                s += Lxb[(w * 16 + qq) * 32 + k];
            int n = q0 + qq;
            if (n < GG)
                g_Hd[base + (size_t)n * 32 + k] = s * sm[OFF_TOT + qq];
        }
        if (c + 1 < 33) {
#pragma unroll
            for (int s = 0; s < 4; s++)
                sm[OFF_QB + tid + s * 512] = nxt[s];
        }
        __syncthreads();
    }
}

// ---------------------------------------------------------------------------
// Kernel C: output projection (unchanged)
// ---------------------------------------------------------------------------
__global__ __launch_bounds__(256) void out_gemm(
    const float* __restrict__ Wout, float* __restrict__ out)
{
    __shared__ float Ash[16][132];
    __shared__ float Bsh[16][68];

    const int tid = threadIdx.x;
    const int m0 = blockIdx.x * 128;
    const int n0 = blockIdx.y * 64;
    const int cx = tid & 15;
    const int ry = tid >> 4;

    u64 acc2[8][2];
#pragma unroll
    for (int i = 0; i < 8; i++) { acc2[i][0] = 0ull; acc2[i][1] = 0ull; }

    for (int d0 = 0; d0 < 256; d0 += 16) {
#pragma unroll
        for (int i = 0; i < 2; i++) {
            int fid = tid + i * 256;
            int row = fid >> 2;
            int cg  = (fid & 3) * 4;
            int m   = m0 + row;
            int cc  = d0 + cg;
            float4 v = make_float4(0.f, 0.f, 0.f, 0.f);
            if (m < MROWS)
                v = *(const float4*)(g_Hd + (size_t)(cc >> 5) * MROWS * DKC +
                                     (size_t)m * DKC + (cc & 31));
            Ash[cg + 0][row] = v.x;
            Ash[cg + 1][row] = v.y;
            Ash[cg + 2][row] = v.z;
            Ash[cg + 3][row] = v.w;
        }
        {
            int d  = tid >> 4;
            int nn = (tid & 15) * 4;
            float4 v = *(const float4*)(Wout + (size_t)(d0 + d) * EE + n0 + nn);
            *(float4*)&Bsh[d][nn] = v;
        }
        __syncthreads();

#pragma unroll
        for (int d = 0; d < 16; d++) {
            float4 a0 = *(const float4*)&Ash[d][ry * 4];
            float4 a1 = *(const float4*)&Ash[d][64 + ry * 4];
            ulonglong2 bv = *(const ulonglong2*)&Bsh[d][cx * 4];
            float ar[8] = {a0.x, a0.y, a0.z, a0.w, a1.x, a1.y, a1.z, a1.w};
#pragma unroll
            for (int i = 0; i < 8; i++) {
                u64 a2 = pk2(ar[i], ar[i]);
                FMA2(acc2[i][0], a2, bv.x);
                FMA2(acc2[i][1], a2, bv.y);
            }
        }
        __syncthreads();
    }

#pragma unroll
    for (int i = 0; i < 8; i++) {
        int row = (i < 4) ? (ry * 4 + i) : (64 + ry * 4 + (i - 4));
        int m = m0 + row;
        if (m >= MROWS) continue;
        float2 f0 = upk2(acc2[i][0]);
        float2 f1 = upk2(acc2[i][1]);
        float accr[4] = {f0.x, f0.y, f1.x, f1.y};
#pragma unroll
        for (int j = 0; j < 4; j++) {
            out[(size_t)m * EE + n0 + cx * 4 + j] = accr[j];
        }
    }
}

// ---------------------------------------------------------------------------
extern "C" void kernel_launch(void* const* d_in, const int* in_sizes, int n_in,
                              void* d_out, int out_size)
{
    (void)in_sizes; (void)n_in; (void)out_size;
    const float* q    = (const float*)d_in[0];
    const float* h    = (const float*)d_in[1];
    const float* Wq   = (const float*)d_in[2];
    const float* Wk   = (const float*)d_in[3];
    const float* Wv   = (const float*)d_in[4];
    const float* W1   = (const float*)d_in[5];
    const float* W2   = (const float*)d_in[6];
    const float* W3   = (const float*)d_in[7];
    const float* W4   = (const float*)d_in[8];
    const float* W5   = (const float*)d_in[9];
    const float* W6   = (const float*)d_in[10];
    const float* Wout = (const float*)d_in[11];
    float* out = (float*)d_out;

    const int SMEM_ATTN = SMEM_FLOATS * (int)sizeof(float);  // 206912 B
    cudaFuncSetAttribute(attn_kernel,
                         cudaFuncAttributeMaxDynamicSharedMemorySize, SMEM_ATTN);

    proj_gemm<<<774, 256>>>(q, h, Wq, Wk, Wv, W1, W2, W3, W4, W5, W6);

    dim3 gridA(BB, HH);
    attn_kernel<<<gridA, 512, SMEM_ATTN>>>();

    dim3 gridO((MROWS + 127) / 128, 4);
    out_gemm<<<gridO, 256>>>(Wout, out);
}